// round 5
// baseline (speedup 1.0000x reference)
#include <cuda_runtime.h>
#include <cuda_bf16.h>

#define NUM_CLASSES 1024
#define FEAT_DIM    512
#define BATCH       16384
#define ALPHA       0.5f
#define MAXC        192   // cap on tracked samples/class (Poisson(16): max ~40)
#define SPLIT       4     // blocks per class in cl_main

// Scratch (allocation-free rule): zero-init at module load; cl_main's
// last-arrival block re-zeros g_cnt/g_done so graph replays are consistent.
__device__ int g_cnt[NUM_CLASSES];
__device__ int g_done[NUM_CLASSES];
__device__ int g_slot[NUM_CLASSES * MAXC];

// Kernel 1: zero the new_centers output region AND histogram+scatter labels.
// grid 512 x 256 = 131072 threads: each zeroes one float4 of newc (2MB);
// threads < BATCH also scatter their sample index into the class slot list.
__global__ __launch_bounds__(256) void cl_prep(
    const int* __restrict__ labels,
    float4*    __restrict__ newc4)       // [C*128] float4
{
    int i = blockIdx.x * blockDim.x + threadIdx.x;
    newc4[i] = make_float4(0.f, 0.f, 0.f, 0.f);   // 131072 = C*128 exactly
    if (i < BATCH) {
        int c = labels[i];
        int p = atomicAdd(&g_cnt[c], 1);
        if (p < MAXC) g_slot[c * MAXC + p] = i;
    }
}

// Kernel 2: SPLIT blocks per class (block r of class c handles samples
// j === r mod SPLIT), 4 warps/block, each warp owns whole samples (4
// independent strided float4 loads per sample). Per-sample squared distance
// is a warp shuffle reduce. Each block adds its scaled partial
// (cc/SPLIT - s*partial) into newc via returnless atomics; the zeroed newc
// region makes the four partials sum to cc - s*delta. The 4th-arriving block
// of each class resets g_cnt/g_done for the next replay.
__global__ __launch_bounds__(128) void cl_main(
    const float4* __restrict__ feat,     // [BATCH][128] float4
    const float4* __restrict__ centers,  // [C][128] float4
    float*        __restrict__ result,   // [BATCH]
    float*        __restrict__ newc)     // [C*512] floats (pre-zeroed)
{
    const int c    = blockIdx.x >> 2;        // class
    const int r    = blockIdx.x & 3;         // split id
    const int t    = threadIdx.x;
    const int lane = t & 31;
    const int w    = t >> 5;

    __shared__ float4 sdelta[4][128];        // 8KB per-warp partials

    const int cnt = g_cnt[c];
    const int n   = cnt < MAXC ? cnt : MAXC;

    // Block samples: j = r + 4m.  Warp w: m = w + 4k  ->  j = r + 4w + 16k.
    const int nb = (n > r) ? ((n - r + 3) >> 2) : 0;   // block's sample count

    const int*    slot = g_slot + c * MAXC;
    const float4* crow = centers + c * 128;

    // Per-lane center chunk (float4s lane, lane+32, lane+64, lane+96).
    float4 ctr[4];
    #pragma unroll
    for (int k = 0; k < 4; k++) ctr[k] = crow[lane + 32 * k];

    float4 dl[4];
    #pragma unroll
    for (int k = 0; k < 4; k++) dl[k] = make_float4(0.f, 0.f, 0.f, 0.f);

    for (int m = w; m < nb; m += 4) {
        const int b = slot[r + 4 * m];
        const float4* frow = feat + (size_t)b * 128;

        float4 f[4];
        #pragma unroll
        for (int q = 0; q < 4; q++) f[q] = frow[lane + 32 * q];

        float ss = 0.f;
        #pragma unroll
        for (int q = 0; q < 4; q++) {
            float4 d;
            d.x = ctr[q].x - f[q].x;
            d.y = ctr[q].y - f[q].y;
            d.z = ctr[q].z - f[q].z;
            d.w = ctr[q].w - f[q].w;
            dl[q].x += d.x; dl[q].y += d.y; dl[q].z += d.z; dl[q].w += d.w;
            ss += d.x * d.x + d.y * d.y + d.z * d.z + d.w * d.w;
        }
        #pragma unroll
        for (int o = 16; o; o >>= 1)
            ss += __shfl_xor_sync(0xffffffffu, ss, o);
        if (lane == 0) result[b] = ss;
    }

    // Cross-warp combine of delta partials.
    #pragma unroll
    for (int k = 0; k < 4; k++) sdelta[w][lane + 32 * k] = dl[k];
    __syncthreads();

    float4 dsum = sdelta[0][t];
    #pragma unroll
    for (int ww = 1; ww < 4; ww++) {
        float4 v = sdelta[ww][t];
        dsum.x += v.x; dsum.y += v.y; dsum.z += v.z; dsum.w += v.w;
    }

    // Scaled partial into newc:  Sum_r (cc/4 - s*p_r) = cc - s*delta.
    const float  s  = ALPHA / (float)(cnt + 1);
    const float4 cc = crow[t];
    float* dst = newc + c * FEAT_DIM + 4 * t;
    atomicAdd(dst + 0, 0.25f * cc.x - s * dsum.x);   // returnless -> RED
    atomicAdd(dst + 1, 0.25f * cc.y - s * dsum.y);
    atomicAdd(dst + 2, 0.25f * cc.z - s * dsum.z);
    atomicAdd(dst + 3, 0.25f * cc.w - s * dsum.w);

    // Last of the 4 class blocks resets the counters for the next replay.
    if (t == 0) {
        int v = atomicAdd(&g_done[c], 1);
        if (v == SPLIT - 1) {
            g_cnt[c]  = 0;
            g_done[c] = 0;
        }
    }
}

extern "C" void kernel_launch(void* const* d_in, const int* in_sizes, int n_in,
                              void* d_out, int out_size) {
    const float* features = (const float*)d_in[0];   // 16384*512
    const float* centers  = (const float*)d_in[1];   // 1024*512
    const int*   labels   = (const int*)  d_in[2];   // 16384

    float* out        = (float*)d_out;
    float* result     = out;            // [16384]
    float* newcenters = out + BATCH;    // [1024*512], 64KB offset -> 16B aligned

    cl_prep<<<512, 256>>>(labels, (float4*)newcenters);

    cl_main<<<SPLIT * NUM_CLASSES, 128>>>(
        (const float4*)features,
        (const float4*)centers,
        result,
        newcenters);
}

// round 6
// speedup vs baseline: 1.2642x; 1.2642x over previous
#include <cuda_runtime.h>
#include <cuda_bf16.h>

#define NUM_CLASSES 1024
#define FEAT_DIM    512
#define BATCH       16384
#define ALPHA       0.5f
#define MAXC        192   // cap on tracked samples/class (Poisson(16): max ~40)

// Scratch (allocation-free rule): zero-init at module load; cl_main re-zeros
// g_cnt in its epilogue so every graph replay sees zeros.
__device__ int g_cnt[NUM_CLASSES];
__device__ int g_slot[NUM_CLASSES * MAXC];

// Kernel 1: histogram + scatter sample indices into per-class slots.
__global__ __launch_bounds__(256) void cl_hist_scatter(const int* __restrict__ labels) {
    int i = blockIdx.x * blockDim.x + threadIdx.x;
    if (i < BATCH) {
        int c = labels[i];
        int p = atomicAdd(&g_cnt[c], 1);
        if (p < MAXC) g_slot[c * MAXC + p] = i;
    }
}

// Kernel 2: one block per class, 8 warps. Warp w owns samples j = w + 8m.
// Lane covers 16 floats of the 512-row as 4 strided float4 loads. Slot
// indices for the whole warp are preloaded once (lane m holds sample m's
// index) and broadcast by shuffle, so the loop has no dependent index load.
// Per-sample squared distance is a warp shuffle reduce (no block barrier in
// the loop); delta is combined across the 8 warps once via smem.
__global__ __launch_bounds__(256) void cl_main(
    const float4* __restrict__ feat,     // [BATCH][128] float4
    const float4* __restrict__ centers,  // [C][128] float4
    float*        __restrict__ result,   // [BATCH]
    float4*       __restrict__ newc)     // [C][128] float4
{
    const int c    = blockIdx.x;
    const int t    = threadIdx.x;
    const int lane = t & 31;
    const int w    = t >> 5;

    __shared__ float4 sdelta[8][128];    // 16KB per-warp delta partials

    const int cnt = g_cnt[c];
    const int n   = cnt < MAXC ? cnt : MAXC;

    // Warp w handles samples j = w + 8m, m = 0..nws-1.
    const int nws = (n > w) ? ((n - w + 7) >> 3) : 0;

    const int*    slot = g_slot + c * MAXC;
    const float4* crow = centers + c * 128;

    // Preload this warp's sample indices: lane m -> slot[w + 8m].
    int myidx = 0;
    if (lane < nws) myidx = slot[w + 8 * lane];

    // Issue the FIRST sample's feature loads before touching the center row,
    // so the DRAM fetch overlaps the center load latency.
    float4 f[4];
    int b_cur = __shfl_sync(0xffffffffu, myidx, 0);
    if (nws > 0) {
        const float4* frow = feat + (size_t)b_cur * 128;
        #pragma unroll
        for (int q = 0; q < 4; q++) f[q] = frow[lane + 32 * q];
    }

    // Per-lane center chunk (float4s lane, lane+32, lane+64, lane+96).
    float4 ctr[4];
    #pragma unroll
    for (int k = 0; k < 4; k++) ctr[k] = crow[lane + 32 * k];

    float4 dl[4];
    #pragma unroll
    for (int k = 0; k < 4; k++) dl[k] = make_float4(0.f, 0.f, 0.f, 0.f);

    for (int m = 0; m < nws; m++) {
        float ss = 0.f;
        #pragma unroll
        for (int q = 0; q < 4; q++) {
            float4 d;
            d.x = ctr[q].x - f[q].x;
            d.y = ctr[q].y - f[q].y;
            d.z = ctr[q].z - f[q].z;
            d.w = ctr[q].w - f[q].w;
            dl[q].x += d.x; dl[q].y += d.y; dl[q].z += d.z; dl[q].w += d.w;
            ss += d.x * d.x + d.y * d.y + d.z * d.z + d.w * d.w;
        }

        const int b_out = b_cur;

        // Issue next sample's loads before the reduce chain.
        if (m + 1 < nws) {
            b_cur = __shfl_sync(0xffffffffu, myidx, m + 1);
            const float4* frow = feat + (size_t)b_cur * 128;
            #pragma unroll
            for (int q = 0; q < 4; q++) f[q] = frow[lane + 32 * q];
        }

        #pragma unroll
        for (int o = 16; o; o >>= 1)
            ss += __shfl_xor_sync(0xffffffffu, ss, o);
        if (lane == 0) result[b_out] = ss;
    }

    // Cross-warp delta combine (one block barrier total).
    #pragma unroll
    for (int k = 0; k < 4; k++) sdelta[w][lane + 32 * k] = dl[k];
    __syncthreads();

    // Threads 0..127 finish the combine and write the new center row.
    if (t < 128) {
        float4 dsum = sdelta[0][t];
        #pragma unroll
        for (int ww = 1; ww < 8; ww++) {
            float4 v = sdelta[ww][t];
            dsum.x += v.x; dsum.y += v.y; dsum.z += v.z; dsum.w += v.w;
        }

        const float  s  = ALPHA / (float)(cnt + 1);
        const float4 cc = crow[t];           // L1 hit (row already resident)
        float4 nc;
        nc.x = cc.x - dsum.x * s;
        nc.y = cc.y - dsum.y * s;
        nc.z = cc.z - dsum.z * s;
        nc.w = cc.w - dsum.w * s;
        newc[c * 128 + t] = nc;
    }

    if (t == 0) g_cnt[c] = 0;   // leave scratch zeroed for the next replay
}

extern "C" void kernel_launch(void* const* d_in, const int* in_sizes, int n_in,
                              void* d_out, int out_size) {
    const float* features = (const float*)d_in[0];   // 16384*512
    const float* centers  = (const float*)d_in[1];   // 1024*512
    const int*   labels   = (const int*)  d_in[2];   // 16384

    float* out        = (float*)d_out;
    float* result     = out;            // [16384]
    float* newcenters = out + BATCH;    // [1024*512], 64KB offset -> 16B aligned

    cl_hist_scatter<<<BATCH / 256, 256>>>(labels);

    cl_main<<<NUM_CLASSES, 256>>>(
        (const float4*)features,
        (const float4*)centers,
        result,
        (float4*)newcenters);
}